// round 3
// baseline (speedup 1.0000x reference)
#include <cuda_runtime.h>
#include <cstdint>

// DepthDeformConv: modulated deformable conv 3x3, s=1, p=1, d=1.
// B=4, C=64, H=W=128, O=64, K=9, fp32. Output (4,64,128,128) fp32.
//
// One block per (b, y) row: 512 blocks x 256 threads, 2 blocks/SM.
// Each thread computes an 8o x 4pix output tile, full K=576 accumulation in
// registers (no k-split). K is processed in 4 chunks of 144 (16 c x 9 k):
//   - stage weight chunk [64][144] into smem (once per block per chunk)
//   - gather: jobs = (k, pix); bilinear meta computed once in registers,
//     reused across the 16 channels of the chunk; col[144][128] in smem
//   - FMA: packed fma.rn.f32x2 over pixel pairs, 8x4 tile per thread

#define HW 128
#define PLANE 16384
#define CIN 64
#define OOUT 64
#define CKTOT 576
#define CHUNK 144           // 16 c * 9 k
#define NCHUNK 4
#define COL_PITCH 128       // floats (512B)
#define W_PITCH 148         // floats (592B) -> conflict-free 8-row reads
#define NTHREADS 256

#define OFF_W   73728                       // col: [0, 73728)
#define SMEM_TOTAL (73728 + 64 * W_PITCH * 4)   // 73728 + 37888 = 111616

typedef unsigned long long ull;

__device__ __forceinline__ ull pack2(float lo, float hi) {
    ull d;
    asm("mov.b64 %0, {%1, %2};" : "=l"(d) : "f"(lo), "f"(hi));
    return d;
}
__device__ __forceinline__ float2 unpack2(ull v) {
    float2 r;
    asm("mov.b64 {%0, %1}, %2;" : "=f"(r.x), "=f"(r.y) : "l"(v));
    return r;
}
__device__ __forceinline__ ull fma2(ull a, ull b, ull c) {
    ull d;
    asm("fma.rn.f32x2 %0, %1, %2, %3;" : "=l"(d) : "l"(a), "l"(b), "l"(c));
    return d;
}

extern __shared__ char smraw[];

__global__ __launch_bounds__(NTHREADS, 2)
void ddc_main(const float* __restrict__ input,
              const float* __restrict__ offset,
              const float* __restrict__ mask,
              const float* __restrict__ weight,
              const float* __restrict__ bias,
              float* __restrict__ out)
{
    float* col = (float*)smraw;
    float* wsm = (float*)(smraw + OFF_W);

    const int tid = threadIdx.x;
    const int bid = blockIdx.x;
    const int y = bid & 127;
    const int b = bid >> 7;
    const int op8  = tid & 7;      // 8 groups of 8 output channels
    const int pixg = tid >> 3;     // 32 groups of 4 pixels

    const float* inb = input + (size_t)b * CIN * PLANE;

    ull acc[8][2];
    #pragma unroll
    for (int j = 0; j < 8; j++) { acc[j][0] = 0ULL; acc[j][1] = 0ULL; }

    for (int cc = 0; cc < NCHUNK; cc++) {
        const int c0 = cc * 16;
        __syncthreads();    // previous FMA phase done reading col/wsm

        // ---- stage weight chunk [64][144] -> wsm (pitch 148) ----
        {
            int o = tid >> 2, q = tid & 3;
            const float4* src = (const float4*)(weight + (size_t)o * CKTOT + cc * CHUNK) + q * 9;
            float4* dst = (float4*)(wsm + o * W_PITCH) + q * 9;
            #pragma unroll
            for (int j = 0; j < 9; j++) dst[j] = src[j];
        }

        // ---- gather: 1152 (k,pix) jobs, each loops 16 channels ----
        for (int i = tid; i < 9 * HW; i += NTHREADS) {
            int pix = i & 127;
            int k   = i >> 7;                  // 0..8
            int ky  = k / 3;
            int kx  = k - ky * 3;

            int ob = ((b * 18 + 2 * k) * HW + y) * HW + pix;
            float oy = __ldg(offset + ob);
            float ox = __ldg(offset + ob + PLANE);
            float m  = __ldg(mask + ((b * 9 + k) * HW + y) * HW + pix);

            float py = (float)(y - 1 + ky) + oy;
            float px = (float)(pix - 1 + kx) + ox;
            float y0f = floorf(py), x0f = floorf(px);
            int y0 = (int)y0f, x0 = (int)x0f;
            float wy = py - y0f, wx = px - x0f;
            int y1 = y0 + 1, x1 = x0 + 1;

            float vy0 = (y0 >= 0 && y0 < HW) ? 1.f : 0.f;
            float vy1 = (y1 >= 0 && y1 < HW) ? 1.f : 0.f;
            float vx0 = (x0 >= 0 && x0 < HW) ? 1.f : 0.f;
            float vx1 = (x1 >= 0 && x1 < HW) ? 1.f : 0.f;
            int yc0 = min(max(y0, 0), HW - 1);
            int yc1 = min(max(y1, 0), HW - 1);
            int xc0 = min(max(x0, 0), HW - 1);
            int xc1 = min(max(x1, 0), HW - 1);

            float w00 = (1.f - wy) * (1.f - wx) * m * vy0 * vx0;
            float w01 = (1.f - wy) * wx         * m * vy0 * vx1;
            float w10 = wy         * (1.f - wx) * m * vy1 * vx0;
            float w11 = wy         * wx         * m * vy1 * vx1;

            int i00 = yc0 * HW + xc0;
            int i01 = yc0 * HW + xc1;
            int i10 = yc1 * HW + xc0;
            int i11 = yc1 * HW + xc1;

            const float* p = inb + (size_t)c0 * PLANE;
            float* cdst = col + k * COL_PITCH + pix;
            #pragma unroll 4
            for (int cl = 0; cl < 16; cl++) {
                float v = w00 * __ldg(p + i00) + w01 * __ldg(p + i01)
                        + w10 * __ldg(p + i10) + w11 * __ldg(p + i11);
                cdst[cl * 9 * COL_PITCH] = v;
                p += PLANE;
            }
        }
        __syncthreads();

        // ---- FMA: 36 iterations of 4 ck, 8o x 4pix tile ----
        #pragma unroll 1
        for (int ck = 0; ck < CHUNK; ck += 4) {
            float4 wv[8];
            #pragma unroll
            for (int j = 0; j < 8; j++)
                wv[j] = *(const float4*)(wsm + (op8 * 8 + j) * W_PITCH + ck);
            ulonglong2 cv[4];
            #pragma unroll
            for (int u = 0; u < 4; u++)
                cv[u] = *(const ulonglong2*)(col + (ck + u) * COL_PITCH + pixg * 4);
            #pragma unroll
            for (int u = 0; u < 4; u++) {
                #pragma unroll
                for (int j = 0; j < 8; j++) {
                    float w = ((const float*)&wv[j])[u];
                    ull wp = pack2(w, w);
                    acc[j][0] = fma2(wp, cv[u].x, acc[j][0]);
                    acc[j][1] = fma2(wp, cv[u].y, acc[j][1]);
                }
            }
        }
    }

    // ---- epilogue ----
    #pragma unroll
    for (int j = 0; j < 8; j++) {
        int o = op8 * 8 + j;
        float bv = __ldg(bias + o);
        float2 a0 = unpack2(acc[j][0]);
        float2 a1 = unpack2(acc[j][1]);
        float4 r;
        r.x = a0.x + bv; r.y = a0.y + bv;
        r.z = a1.x + bv; r.w = a1.y + bv;
        *(float4*)(out + (size_t)(b * OOUT + o) * PLANE + y * HW + pixg * 4) = r;
    }
}

extern "C" void kernel_launch(void* const* d_in, const int* in_sizes, int n_in,
                              void* d_out, int out_size)
{
    const float* input  = (const float*)d_in[0];
    // d_in[1] = depth, unused by the reference computation
    const float* offset = (const float*)d_in[2];
    const float* mask   = (const float*)d_in[3];
    const float* weight = (const float*)d_in[4];
    const float* bias   = (const float*)d_in[5];
    float* out = (float*)d_out;

    cudaFuncSetAttribute(ddc_main,
                         cudaFuncAttributeMaxDynamicSharedMemorySize, SMEM_TOTAL);

    // grid: b (4) * y (128) = 512 blocks
    ddc_main<<<512, NTHREADS, SMEM_TOTAL>>>(input, offset, mask, weight, bias, out);
}

// round 4
// speedup vs baseline: 3.6508x; 3.6508x over previous
#include <cuda_runtime.h>
#include <cstdint>

// DepthDeformConv: modulated deformable conv 3x3, s=1, p=1, d=1.
// B=4, C=64, H=W=128, O=64, K=9, fp32. Output (4,64,128,128) fp32.
//
// One block per (b, y) row: 512 blocks x 256 threads, 2 blocks/SM.
// K=576 processed in 4 chunks of 144 (16 c x 9 k):
//   - stage weight chunk [64][144] into smem (coalesced, once per chunk)
//   - gather: jobs = (k, pix); bilinear meta computed once in registers,
//     reused across 16 channels; col[144][128] in smem
//   - FMA: warp = 8-output group, lane = 4-pixel group.
//     Weight LDS is warp-broadcast (1 wavefront), col LDS lane-consecutive
//     (conflict-free). Packed fma.rn.f32x2, 8o x 4pix tile per thread.

#define HW 128
#define PLANE 16384
#define CIN 64
#define OOUT 64
#define CKTOT 576
#define CHUNK 144           // 16 c * 9 k
#define NCHUNK 4
#define COL_PITCH 128       // floats
#define NTHREADS 256

#define OFF_W   73728                        // col: [0, 73728)
#define SMEM_TOTAL (73728 + 64 * CHUNK * 4)  // 73728 + 36864 = 110592

typedef unsigned long long ull;

__device__ __forceinline__ ull pack2(float lo, float hi) {
    ull d;
    asm("mov.b64 %0, {%1, %2};" : "=l"(d) : "f"(lo), "f"(hi));
    return d;
}
__device__ __forceinline__ float2 unpack2(ull v) {
    float2 r;
    asm("mov.b64 {%0, %1}, %2;" : "=f"(r.x), "=f"(r.y) : "l"(v));
    return r;
}
__device__ __forceinline__ ull fma2(ull a, ull b, ull c) {
    ull d;
    asm("fma.rn.f32x2 %0, %1, %2, %3;" : "=l"(d) : "l"(a), "l"(b), "l"(c));
    return d;
}

extern __shared__ char smraw[];

__global__ __launch_bounds__(NTHREADS, 2)
void ddc_main(const float* __restrict__ input,
              const float* __restrict__ offset,
              const float* __restrict__ mask,
              const float* __restrict__ weight,
              const float* __restrict__ bias,
              float* __restrict__ out)
{
    float* col = (float*)smraw;
    float* wsm = (float*)(smraw + OFF_W);

    const int tid = threadIdx.x;
    const int bid = blockIdx.x;
    const int y = bid & 127;
    const int b = bid >> 7;
    const int wid  = tid >> 5;     // warp = 8-output group (o0 = wid*8)
    const int lane = tid & 31;     // lane = 4-pixel group (pix0 = lane*4)

    const float* inb = input + (size_t)b * CIN * PLANE;

    ull acc[8][2];
    #pragma unroll
    for (int j = 0; j < 8; j++) { acc[j][0] = 0ULL; acc[j][1] = 0ULL; }

    for (int cc = 0; cc < NCHUNK; cc++) {
        const int c0 = cc * 16;
        __syncthreads();    // previous FMA phase done reading col/wsm

        // ---- stage weight chunk [64][144] -> wsm (contiguous, coalesced) ----
        {
            int o = tid >> 2, q = tid & 3;
            const float4* src = (const float4*)(weight + (size_t)o * CKTOT + cc * CHUNK) + q * 9;
            float4* dst = (float4*)(wsm + o * CHUNK) + q * 9;
            #pragma unroll
            for (int j = 0; j < 9; j++) dst[j] = src[j];
        }

        // ---- gather: 1152 (k,pix) jobs, each loops 16 channels ----
        for (int i = tid; i < 9 * HW; i += NTHREADS) {
            int pix = i & 127;
            int k   = i >> 7;                  // 0..8
            int ky  = k / 3;
            int kx  = k - ky * 3;

            int ob = ((b * 18 + 2 * k) * HW + y) * HW + pix;
            float oy = __ldg(offset + ob);
            float ox = __ldg(offset + ob + PLANE);
            float m  = __ldg(mask + ((b * 9 + k) * HW + y) * HW + pix);

            float py = (float)(y - 1 + ky) + oy;
            float px = (float)(pix - 1 + kx) + ox;
            float y0f = floorf(py), x0f = floorf(px);
            int y0 = (int)y0f, x0 = (int)x0f;
            float wy = py - y0f, wx = px - x0f;
            int y1 = y0 + 1, x1 = x0 + 1;

            float vy0 = (y0 >= 0 && y0 < HW) ? 1.f : 0.f;
            float vy1 = (y1 >= 0 && y1 < HW) ? 1.f : 0.f;
            float vx0 = (x0 >= 0 && x0 < HW) ? 1.f : 0.f;
            float vx1 = (x1 >= 0 && x1 < HW) ? 1.f : 0.f;
            int yc0 = min(max(y0, 0), HW - 1);
            int yc1 = min(max(y1, 0), HW - 1);
            int xc0 = min(max(x0, 0), HW - 1);
            int xc1 = min(max(x1, 0), HW - 1);

            float w00 = (1.f - wy) * (1.f - wx) * m * vy0 * vx0;
            float w01 = (1.f - wy) * wx         * m * vy0 * vx1;
            float w10 = wy         * (1.f - wx) * m * vy1 * vx0;
            float w11 = wy         * wx         * m * vy1 * vx1;

            int i00 = yc0 * HW + xc0;
            int i01 = yc0 * HW + xc1;
            int i10 = yc1 * HW + xc0;
            int i11 = yc1 * HW + xc1;

            const float* p = inb + (size_t)c0 * PLANE;
            float* cdst = col + k * COL_PITCH + pix;
            #pragma unroll 4
            for (int cl = 0; cl < 16; cl++) {
                float v = w00 * __ldg(p + i00) + w01 * __ldg(p + i01)
                        + w10 * __ldg(p + i10) + w11 * __ldg(p + i11);
                cdst[cl * 9 * COL_PITCH] = v;
                p += PLANE;
            }
        }
        __syncthreads();

        // ---- FMA: 36 iterations of 4 ck ----
        // warp-broadcast weight reads; lane-consecutive col reads
        #pragma unroll 1
        for (int ck = 0; ck < CHUNK; ck += 4) {
            float4 wv[8];
            #pragma unroll
            for (int j = 0; j < 8; j++)
                wv[j] = *(const float4*)(wsm + (wid * 8 + j) * CHUNK + ck);
            ulonglong2 cv[4];
            #pragma unroll
            for (int u = 0; u < 4; u++)
                cv[u] = *(const ulonglong2*)(col + (ck + u) * COL_PITCH + lane * 4);
            #pragma unroll
            for (int u = 0; u < 4; u++) {
                #pragma unroll
                for (int j = 0; j < 8; j++) {
                    float w = ((const float*)&wv[j])[u];
                    ull wp = pack2(w, w);
                    acc[j][0] = fma2(wp, cv[u].x, acc[j][0]);
                    acc[j][1] = fma2(wp, cv[u].y, acc[j][1]);
                }
            }
        }
    }

    // ---- epilogue: warp wid writes outputs o = wid*8 .. wid*8+7 ----
    #pragma unroll
    for (int j = 0; j < 8; j++) {
        int o = wid * 8 + j;
        float bv = __ldg(bias + o);
        float2 a0 = unpack2(acc[j][0]);
        float2 a1 = unpack2(acc[j][1]);
        float4 r;
        r.x = a0.x + bv; r.y = a0.y + bv;
        r.z = a1.x + bv; r.w = a1.y + bv;
        *(float4*)(out + (size_t)(b * OOUT + o) * PLANE + y * HW + lane * 4) = r;
    }
}

extern "C" void kernel_launch(void* const* d_in, const int* in_sizes, int n_in,
                              void* d_out, int out_size)
{
    const float* input  = (const float*)d_in[0];
    // d_in[1] = depth, unused by the reference computation
    const float* offset = (const float*)d_in[2];
    const float* mask   = (const float*)d_in[3];
    const float* weight = (const float*)d_in[4];
    const float* bias   = (const float*)d_in[5];
    float* out = (float*)d_out;

    cudaFuncSetAttribute(ddc_main,
                         cudaFuncAttributeMaxDynamicSharedMemorySize, SMEM_TOTAL);

    // grid: b (4) * y (128) = 512 blocks
    ddc_main<<<512, NTHREADS, SMEM_TOTAL>>>(input, offset, mask, weight, bias, out);
}

// round 5
// speedup vs baseline: 3.8552x; 1.0560x over previous
#include <cuda_runtime.h>
#include <cstdint>

// DepthDeformConv: modulated deformable conv 3x3, s=1, p=1, d=1.
// B=4, C=64, H=W=128, O=64, K=9, fp32. Output (4,64,128,128) fp32.
//
// One block per (b, y) row: 512 blocks x 256 threads, 2 blocks/SM.
// K=576 in 4 chunks of 144 (16 c x 9 k). Per chunk:
//   - stage o-transposed weights g_wt[ck][64] -> wsm_t (coalesced)
//   - gather (proven R4 code): (k,pix) jobs, bilinear meta in regs,
//     reused over 16 channels; col[144][128] in smem
//   - FMA: warp = 16-output group x ck-half; lane = 4-pixel group.
//     Weight LDS.128 (broadcast) yields o-pairs pre-packed for fma2
//     (no per-weight pack2). col packs: only 4 per ck. acc = 8 o-pairs
//     x 4 pix in u64 (even-o, odd-o) lanes.
//   - final: 2-way ck reduction through smem (add.rn.f32x2), bias, STG.128.

#define HW 128
#define PLANE 16384
#define CIN 64
#define OOUT 64
#define CKTOT 576
#define CHUNK 144           // 16 c * 9 k
#define NCHUNK 4
#define COL_PITCH 128
#define NTHREADS 256

#define OFF_W   73728                        // col: [0, 73728)
#define SMEM_TOTAL (73728 + CHUNK * 64 * 4)  // 73728 + 36864 = 110592

typedef unsigned long long ull;

__device__ float g_wt[CKTOT * OOUT];   // weight transposed: [ck][o]

__device__ __forceinline__ ull pack2(float lo, float hi) {
    ull d;
    asm("mov.b64 %0, {%1, %2};" : "=l"(d) : "f"(lo), "f"(hi));
    return d;
}
__device__ __forceinline__ float2 unpack2(ull v) {
    float2 r;
    asm("mov.b64 {%0, %1}, %2;" : "=f"(r.x), "=f"(r.y) : "l"(v));
    return r;
}
__device__ __forceinline__ ull fma2(ull a, ull b, ull c) {
    ull d;
    asm("fma.rn.f32x2 %0, %1, %2, %3;" : "=l"(d) : "l"(a), "l"(b), "l"(c));
    return d;
}
__device__ __forceinline__ ull add2(ull a, ull b) {
    ull d;
    asm("add.rn.f32x2 %0, %1, %2;" : "=l"(d) : "l"(a), "l"(b));
    return d;
}

// one-time weight transpose: g_wt[ck*64 + o] = weight[o*576 + ck]
__global__ __launch_bounds__(256) void k_prep(const float* __restrict__ w) {
    int idx = blockIdx.x * 256 + threadIdx.x;
    if (idx >= OOUT * CKTOT) return;
    int o = idx / CKTOT, ck = idx - o * CKTOT;
    g_wt[ck * OOUT + o] = w[idx];
}

extern __shared__ char smraw[];

__global__ __launch_bounds__(NTHREADS, 2)
void ddc_main(const float* __restrict__ input,
              const float* __restrict__ offset,
              const float* __restrict__ mask,
              const float* __restrict__ bias,
              float* __restrict__ out)
{
    float* col   = (float*)smraw;
    float* wsm_t = (float*)(smraw + OFF_W);    // [144][64]

    const int tid = threadIdx.x;
    const int bid = blockIdx.x;
    const int y = bid & 127;
    const int b = bid >> 7;
    const int wid  = tid >> 5;
    const int lane = tid & 31;     // lane = 4-pixel group
    const int og   = wid & 3;      // o-group: 16 outputs, o base = og*16
    const int ckh  = wid >> 2;     // ck half: [ckh*72, ckh*72+72) per chunk

    const float* inb = input + (size_t)b * CIN * PLANE;

    // acc[j][p]: o-pair j (o = og*16+2j, +2j+1), pixel p (pix = lane*4+p)
    ull acc[8][4];
    #pragma unroll
    for (int j = 0; j < 8; j++)
        #pragma unroll
        for (int p = 0; p < 4; p++) acc[j][p] = 0ULL;

    for (int cc = 0; cc < NCHUNK; cc++) {
        const int c0 = cc * 16;
        __syncthreads();    // previous FMA phase done reading col/wsm_t

        // ---- stage transposed weight chunk [144][64] (coalesced copy) ----
        {
            const float4* src = (const float4*)(g_wt + cc * CHUNK * OOUT);
            float4* dst = (float4*)wsm_t;
            #pragma unroll
            for (int i = 0; i < 9; i++)
                dst[tid + i * NTHREADS] = src[tid + i * NTHREADS];
        }

        // ---- gather: 1152 (k,pix) jobs, each loops 16 channels ----
        for (int i = tid; i < 9 * HW; i += NTHREADS) {
            int pix = i & 127;
            int k   = i >> 7;                  // 0..8
            int ky  = k / 3;
            int kx  = k - ky * 3;

            int ob = ((b * 18 + 2 * k) * HW + y) * HW + pix;
            float oy = __ldg(offset + ob);
            float ox = __ldg(offset + ob + PLANE);
            float m  = __ldg(mask + ((b * 9 + k) * HW + y) * HW + pix);

            float py = (float)(y - 1 + ky) + oy;
            float px = (float)(pix - 1 + kx) + ox;
            float y0f = floorf(py), x0f = floorf(px);
            int y0 = (int)y0f, x0 = (int)x0f;
            float wy = py - y0f, wx = px - x0f;
            int y1 = y0 + 1, x1 = x0 + 1;

            float vy0 = (y0 >= 0 && y0 < HW) ? 1.f : 0.f;
            float vy1 = (y1 >= 0 && y1 < HW) ? 1.f : 0.f;
            float vx0 = (x0 >= 0 && x0 < HW) ? 1.f : 0.f;
            float vx1 = (x1 >= 0 && x1 < HW) ? 1.f : 0.f;
            int yc0 = min(max(y0, 0), HW - 1);
            int yc1 = min(max(y1, 0), HW - 1);
            int xc0 = min(max(x0, 0), HW - 1);
            int xc1 = min(max(x1, 0), HW - 1);

            float w00 = (1.f - wy) * (1.f - wx) * m * vy0 * vx0;
            float w01 = (1.f - wy) * wx         * m * vy0 * vx1;
            float w10 = wy         * (1.f - wx) * m * vy1 * vx0;
            float w11 = wy         * wx         * m * vy1 * vx1;

            int i00 = yc0 * HW + xc0;
            int i01 = yc0 * HW + xc1;
            int i10 = yc1 * HW + xc0;
            int i11 = yc1 * HW + xc1;

            const float* p = inb + (size_t)c0 * PLANE;
            float* cdst = col + k * COL_PITCH + pix;
            #pragma unroll 4
            for (int cl = 0; cl < 16; cl++) {
                float v = w00 * __ldg(p + i00) + w01 * __ldg(p + i01)
                        + w10 * __ldg(p + i10) + w11 * __ldg(p + i11);
                cdst[cl * 9 * COL_PITCH] = v;   // row ck = cl*9 + k
                p += PLANE;
            }
        }
        __syncthreads();

        // ---- FMA: ck half [ckh*72, +72), 18 iters of 4 ck ----
        #pragma unroll 1
        for (int ck = ckh * 72; ck < ckh * 72 + 72; ck += 4) {
            #pragma unroll
            for (int u = 0; u < 4; u++) {
                // 4 pixels of this ck row
                float4 cq = *(const float4*)(col + (ck + u) * COL_PITCH + lane * 4);
                ull cp0 = pack2(cq.x, cq.x);
                ull cp1 = pack2(cq.y, cq.y);
                ull cp2 = pack2(cq.z, cq.z);
                ull cp3 = pack2(cq.w, cq.w);
                const float* wrow = wsm_t + (ck + u) * OOUT + og * 16;
                #pragma unroll
                for (int j2 = 0; j2 < 4; j2++) {
                    float4 wq = *(const float4*)(wrow + j2 * 4);  // broadcast
                    ull wp0 = pack2(wq.x, wq.y);   // o-pair (4j2, 4j2+1)
                    ull wp1 = pack2(wq.z, wq.w);   // o-pair (4j2+2, 4j2+3)
                    int j = j2 * 2;
                    acc[j][0] = fma2(wp0, cp0, acc[j][0]);
                    acc[j][1] = fma2(wp0, cp1, acc[j][1]);
                    acc[j][2] = fma2(wp0, cp2, acc[j][2]);
                    acc[j][3] = fma2(wp0, cp3, acc[j][3]);
                    acc[j+1][0] = fma2(wp1, cp0, acc[j+1][0]);
                    acc[j+1][1] = fma2(wp1, cp1, acc[j+1][1]);
                    acc[j+1][2] = fma2(wp1, cp2, acc[j+1][2]);
                    acc[j+1][3] = fma2(wp1, cp3, acc[j+1][3]);
                }
            }
        }
    }

    // ---- reduction across the 2 ck halves (reuse wsm_t area) ----
    ull* pr = (ull*)(smraw + OFF_W);   // [32 o-pairs][128 pix] u64 = 32KB
    __syncthreads();
    if (ckh == 1) {
        #pragma unroll
        for (int j = 0; j < 8; j++) {
            ull* row = pr + (og * 8 + j) * 128 + lane * 4;
            row[0] = acc[j][0]; row[1] = acc[j][1];
            row[2] = acc[j][2]; row[3] = acc[j][3];
        }
    }
    __syncthreads();
    if (ckh == 0) {
        #pragma unroll
        for (int j = 0; j < 8; j++) {
            const ull* row = pr + (og * 8 + j) * 128 + lane * 4;
            int o0 = og * 16 + 2 * j;
            float bv0 = __ldg(bias + o0);
            float bv1 = __ldg(bias + o0 + 1);
            float4 re, ro;
            float2 v;
            v = unpack2(add2(acc[j][0], row[0])); re.x = v.x + bv0; ro.x = v.y + bv1;
            v = unpack2(add2(acc[j][1], row[1])); re.y = v.x + bv0; ro.y = v.y + bv1;
            v = unpack2(add2(acc[j][2], row[2])); re.z = v.x + bv0; ro.z = v.y + bv1;
            v = unpack2(add2(acc[j][3], row[3])); re.w = v.x + bv0; ro.w = v.y + bv1;
            size_t base = (size_t)(b * OOUT + o0) * PLANE + y * HW + lane * 4;
            *(float4*)(out + base)         = re;
            *(float4*)(out + base + PLANE) = ro;
        }
    }
}

extern "C" void kernel_launch(void* const* d_in, const int* in_sizes, int n_in,
                              void* d_out, int out_size)
{
    const float* input  = (const float*)d_in[0];
    // d_in[1] = depth, unused by the reference computation
    const float* offset = (const float*)d_in[2];
    const float* mask   = (const float*)d_in[3];
    const float* weight = (const float*)d_in[4];
    const float* bias   = (const float*)d_in[5];
    float* out = (float*)d_out;

    cudaFuncSetAttribute(ddc_main,
                         cudaFuncAttributeMaxDynamicSharedMemorySize, SMEM_TOTAL);

    k_prep<<<(OOUT * CKTOT + 255) / 256, 256>>>(weight);
    ddc_main<<<512, NTHREADS, SMEM_TOTAL>>>(input, offset, mask, bias, out);
}